// round 8
// baseline (speedup 1.0000x reference)
#include <cuda_runtime.h>
#include <cstdint>

#define B_SZ   64
#define IN_F   8192
#define OUT_F  8192
#define NNZ    262144
#define K8     8
#define SPMM_BLOCKS 740             // 148 SMs * 5 resident blocks
#define UNITS  (OUT_F * 2)          // (row, batch-half) work units
#define THIST_BLOCKS 512

// ---------------- device scratch (no allocations allowed) ----------------
__device__ __align__(16) float  g_t[(size_t)IN_F * B_SZ];   // 2 MB, [col][batch]
__device__ int    g_count[OUT_F];     // zero-init at load; re-zeroed by spmm each call
__device__ int    g_start[OUT_F];
__device__ int    g_cursor[OUT_F];    // after scatter: start + n
__device__ int    g_ticket;           // spmm scheduler; reset by fused scan
__device__ unsigned g_done;           // last-block detector (wraps to 0 each call)
__device__ int    g_c[NNZ];                                  // cols in CSR order
__device__ __align__(16) float g_p[(size_t)NNZ * K8];        // monomial coeffs, CSR order (8MB)

// ------- K1: tanh table + row histogram + FUSED exclusive scan (last block) -
// grid (256,2) = 512 blocks, block (32,8) = 256 threads.
__global__ void tanh_hist_scan_kernel(const float* __restrict__ x,
                                      const int*   __restrict__ rows) {
    __shared__ float tile[32][33];
    int tx = threadIdx.x, ty = threadIdx.y;
    int tid = ty * 32 + tx;
    int flat = (blockIdx.y * gridDim.x + blockIdx.x) * 256 + tid;
    int e0 = flat * 2;                 // 512*256*2 == NNZ
    atomicAdd(&g_count[rows[e0]], 1);
    atomicAdd(&g_count[rows[e0 + 1]], 1);

    int c0 = blockIdx.x * 32, b0 = blockIdx.y * 32;
    const float CLIP = 1.0f - 1e-7f;
#pragma unroll
    for (int i = 0; i < 4; i++) {
        int b = b0 + ty + i * 8;
        float xv = x[(size_t)b * IN_F + c0 + tx];
        // fast tanh: 1 - 2/(exp(2x)+1); exact at +-inf, clipped below
        float e  = __expf(2.0f * xv);
        float t  = 1.0f - 2.0f / (e + 1.0f);
        tile[ty + i * 8][tx] = fminf(fmaxf(t, -CLIP), CLIP);
    }
    __syncthreads();
#pragma unroll
    for (int i = 0; i < 4; i++) {
        int c = c0 + ty + i * 8;
        g_t[(size_t)c * B_SZ + b0 + tx] = tile[tx][ty + i * 8]; // coalesced over b
    }

    // ---- last-block scan over g_count[0..8191] ----
    __threadfence();                   // order this block's hist atomics
    __syncthreads();
    __shared__ int s_last;
    if (tid == 0) s_last = (atomicInc(&g_done, THIST_BLOCKS - 1) == THIST_BLOCKS - 1);
    __syncthreads();
    if (!s_last) return;

    int base = tid * 32;               // 256 threads * 32 counters
    int sum = 0;
#pragma unroll
    for (int j = 0; j < 8; j++) {
        int4 v = *reinterpret_cast<const int4*>(g_count + base + j * 4);
        sum += v.x + v.y + v.z + v.w;
    }
    // block-wide exclusive scan of 256 per-thread sums
    int lane = tid & 31, wid = tid >> 5;
    int inc = sum;
#pragma unroll
    for (int off = 1; off < 32; off <<= 1) {
        int y = __shfl_up_sync(0xFFFFFFFFu, inc, off);
        if (lane >= off) inc += y;
    }
    __shared__ int wsum[8];
    if (lane == 31) wsum[wid] = inc;
    __syncthreads();
    int woff = 0;
    if (wid > 0) {
#pragma unroll
        for (int wI = 0; wI < 7; wI++) if (wI < wid) woff += wsum[wI];
    }
    int run = woff + (inc - sum);      // exclusive offset for this thread
#pragma unroll
    for (int j = 0; j < 8; j++) {
        int4 v = *reinterpret_cast<const int4*>(g_count + base + j * 4);
        int i0 = base + j * 4;
        g_start[i0]     = run; g_cursor[i0]     = run; run += v.x;
        g_start[i0 + 1] = run; g_cursor[i0 + 1] = run; run += v.y;
        g_start[i0 + 2] = run; g_cursor[i0 + 2] = run; run += v.z;
        g_start[i0 + 3] = run; g_cursor[i0 + 3] = run; run += v.w;
    }
    if (tid == 0) g_ticket = 0;
}

// -------- K2: scatter cols + Chebyshev->monomial coeffs, 1 edge/thread -----
__device__ __forceinline__ void cheb2mono(float4 a, float4 b, float4& p0, float4& p1) {
    p0.x = a.x - a.z + b.x - b.z;
    p0.y = a.y - 3.f*a.w + 5.f*b.y - 7.f*b.w;
    p0.z = 2.f*a.z - 8.f*b.x + 18.f*b.z;
    p0.w = 4.f*a.w - 20.f*b.y + 56.f*b.w;
    p1.x = 8.f*b.x - 48.f*b.z;
    p1.y = 16.f*b.y - 112.f*b.w;
    p1.z = 32.f*b.z;
    p1.w = 64.f*b.w;
}

__global__ void scatter_kernel(const int*   __restrict__ rows,
                               const int*   __restrict__ cols,
                               const float* __restrict__ weight) {
    int i = blockIdx.x * blockDim.x + threadIdx.x;   // NNZ threads
    int r = rows[i];
    int c = cols[i];
    const float4* wp = reinterpret_cast<const float4*>(weight + (size_t)i * K8);
    float4 a = wp[0], b = wp[1];
    float4 q0, q1;
    cheb2mono(a, b, q0, q1);
    int p = atomicAdd(&g_cursor[r], 1);
    g_c[p] = c;
    float4* dst = reinterpret_cast<float4*>(g_p + (size_t)p * K8);
    dst[0] = q0;
    dst[1] = q1;
}

// ---------------- K3: main SpMM — (row, batch-half) units, 3-stage pipeline
// One warp per unit; lane owns batch bb+lane. t load per edge = one 128B line.
__global__ void __launch_bounds__(256, 5) spmm_kernel(float* __restrict__ out) {
    int lane = threadIdx.x & 31;

    for (;;) {
        int u;
        if (lane == 0) u = atomicAdd(&g_ticket, 1);
        u = __shfl_sync(0xFFFFFFFFu, u, 0);
        if (u >= UNITS) return;
        int r  = u >> 1;
        int bb = (u & 1) << 5;

        int start = g_start[r];
        int n     = g_cursor[r] - start;      // cursor holds start+n after scatter

        const int*   cp    = g_c + start;
        const float* pp    = g_p + (size_t)start * K8;
        const float* tbase = g_t + bb + lane;

        float acc = 0.0f;

        if (n > 0) {
            float tA[8], tB[8];
            float wA0, wA1, wB0, wB1;
            int   cA, cB, cN;
            size_t wmax = (size_t)n * K8 - 1;

#define LC(base_) __ldg(cp + min((base_) + (lane & 7), n - 1))

#define LTW(tb, w0_, w1_, creg, base_)                                           \
    do {                                                                         \
        _Pragma("unroll")                                                        \
        for (int _i = 0; _i < 8; _i++) {                                         \
            int _cc = __shfl_sync(0xFFFFFFFFu, (creg), _i);                      \
            (tb)[_i] = __ldg(tbase + ((size_t)_cc << 6));                        \
        }                                                                        \
        size_t _w0 = (size_t)(base_) * K8 + lane;                                \
        size_t _w1 = _w0 + 32;                                                   \
        (w0_) = __ldg(pp + (_w0 <= wmax ? _w0 : wmax));                          \
        (w1_) = __ldg(pp + (_w1 <= wmax ? _w1 : wmax));                          \
    } while (0)

#define EDGE(tv, wv, _li, gi)                                                    \
    do {                                                                         \
        if ((gi) < n) {                                                          \
            float q0 = __shfl_sync(0xFFFFFFFFu, (wv), (_li) * 8 + 0);            \
            float q1 = __shfl_sync(0xFFFFFFFFu, (wv), (_li) * 8 + 1);            \
            float q2 = __shfl_sync(0xFFFFFFFFu, (wv), (_li) * 8 + 2);            \
            float q3 = __shfl_sync(0xFFFFFFFFu, (wv), (_li) * 8 + 3);            \
            float q4 = __shfl_sync(0xFFFFFFFFu, (wv), (_li) * 8 + 4);            \
            float q5 = __shfl_sync(0xFFFFFFFFu, (wv), (_li) * 8 + 5);            \
            float q6 = __shfl_sync(0xFFFFFFFFu, (wv), (_li) * 8 + 6);            \
            float q7 = __shfl_sync(0xFFFFFFFFu, (wv), (_li) * 8 + 7);            \
            float h = q7;                                                        \
            h = fmaf(h, (tv), q6);                                               \
            h = fmaf(h, (tv), q5);                                               \
            h = fmaf(h, (tv), q4);                                               \
            h = fmaf(h, (tv), q3);                                               \
            h = fmaf(h, (tv), q2);                                               \
            h = fmaf(h, (tv), q1);                                               \
            h = fmaf(h, (tv), q0);                                               \
            acc += h;                                                            \
        }                                                                        \
    } while (0)

#define COMPUTE(tb, w0_, w1_, base_)                                             \
    do {                                                                         \
        EDGE((tb)[0], (w0_), 0, (base_) + 0);                                    \
        EDGE((tb)[1], (w0_), 1, (base_) + 1);                                    \
        EDGE((tb)[2], (w0_), 2, (base_) + 2);                                    \
        EDGE((tb)[3], (w0_), 3, (base_) + 3);                                    \
        EDGE((tb)[4], (w1_), 0, (base_) + 4);                                    \
        EDGE((tb)[5], (w1_), 1, (base_) + 5);                                    \
        EDGE((tb)[6], (w1_), 2, (base_) + 6);                                    \
        EDGE((tb)[7], (w1_), 3, (base_) + 7);                                    \
    } while (0)

            cA = LC(0);
            cB = LC(8);
            LTW(tA, wA0, wA1, cA, 0);
            for (int base = 0; base < n; base += 16) {
                cN = LC(base + 16);
                LTW(tB, wB0, wB1, cB, base + 8);
                COMPUTE(tA, wA0, wA1, base);
                cB = LC(base + 24);
                LTW(tA, wA0, wA1, cN, base + 16);
                COMPUTE(tB, wB0, wB1, base + 8);
            }
#undef LC
#undef LTW
#undef EDGE
#undef COMPUTE
        }

        if (bb == 0 && lane == 0) g_count[r] = 0;   // reset histogram (safe: n from cursor)

        out[(size_t)(bb + lane) * OUT_F + r] = acc;
    }
}

// ---------------- launcher ----------------
extern "C" void kernel_launch(void* const* d_in, const int* in_sizes, int n_in,
                              void* d_out, int out_size) {
    const float* x      = (const float*)d_in[0];   // [64, 8192]
    const float* weight = (const float*)d_in[1];   // [262144, 8]
    const int*   rows   = (const int*)  d_in[2];   // [262144]
    const int*   cols   = (const int*)  d_in[3];   // [262144]
    float*       out    = (float*)d_out;           // [64, 8192]

    dim3 tgrid(IN_F / 32, B_SZ / 32);              // 512 blocks
    dim3 tblk(32, 8);
    tanh_hist_scan_kernel<<<tgrid, tblk>>>(x, rows);
    scatter_kernel       <<<NNZ / 256, 256>>>(rows, cols, weight);
    spmm_kernel          <<<SPMM_BLOCKS, 256>>>(out);
}